// round 15
// baseline (speedup 1.0000x reference)
#include <cuda_runtime.h>

// ConvSBS fused contraction, P=6 (3 pixel-pairs/warp), f32x2 SIMD.
// Cores in L1-cached global table (LDG), channels in packed pixel-pair tables.
// channels: [2, 8, 128, 128, 4] f32 ; cores: [4, 2, 8, 8, 4, 4] f32 ; out: [8,127,127,16] f32

typedef unsigned long long ull;

__device__ __forceinline__ ull pk2(float lo, float hi) {
    ull d; asm("mov.b64 %0, {%1, %2};" : "=l"(d) : "f"(lo), "f"(hi)); return d;
}
__device__ __forceinline__ float2 up2(ull v) {
    float2 r; asm("mov.b64 {%0, %1}, %2;" : "=f"(r.x), "=f"(r.y) : "l"(v)); return r;
}
__device__ __forceinline__ ull fma2(ull a, ull b, ull c) {
    ull d; asm("fma.rn.f32x2 %0, %1, %2, %3;" : "=l"(d) : "l"(a), "l"(b), "l"(c)); return d;
}
__device__ __forceinline__ ull mul2(ull a, ull b) {
    ull d; asm("mul.rn.f32x2 %0, %1, %2;" : "=l"(d) : "l"(a), "l"(b)); return d;
}
__device__ __forceinline__ ull add2(ull a, ull b) {
    ull d; asm("add.rn.f32x2 %0, %1, %2;" : "=l"(d) : "l"(a), "l"(b)); return d;
}

#define BATCH 8
#define H 128
#define W 128
#define OH 127
#define OW 127
#define GXG 22                               // groups of 6 px per row (22*6=132 >= 127)
#define ROWG (OH * GXG)                      // 2794
#define TOT_GROUPS (BATCH * ROWG)            // 22352

#define WARPS_PER_CTA 8
#define NTHREADS (WARPS_PER_CTA * 32)
#define NCTAS 296
#define NPAIR 3

// Packed pixel-pair channel tables: [ch][b][y][a][j]
//   chE[..][j] = (px 2j,   px 2j+1) ; chO[..][j] = (px 2j+1, px min(2j+2,127))
__device__ ull g_chE[2][BATCH][H][4][64];
__device__ ull g_chO[2][BATCH][H][4][64];
// Relayouted cores: g_core[(bi*16 + ac)*64 + lr], bi = t*2+q, ac = a*4+c.
__device__ float g_core[8192];

// Per-pair scratch: 512 ull (unpadded).
//   M element (bi,row,col) at ull idx bi*64 + row*8 + col.
//   Overlays (written only after the overlapped M blocks are dead):
//     Bsm[rs][k][i] at rs*82 + k*10 + i   (max 323)
//     Psm at 336 + (q*8+i)*10 + q*8 + o8  (max 501)
#define PAIR_ULL 512
#define WARP_ULL (NPAIR * PAIR_ULL)
#define SMEM_F  (WARPS_PER_CTA * WARP_ULL * 2)

__global__ void setup_kernel(const float* __restrict__ channels,
                             const float* __restrict__ cores) {
    int idx = blockIdx.x * blockDim.x + threadIdx.x;   // 524288 threads
    if (idx < 8192) {
        int c4 = idx & 3, a = (idx >> 2) & 3, r = (idx >> 4) & 7;
        int l = (idx >> 7) & 7, q = (idx >> 10) & 1, t = idx >> 11;
        g_core[(((t * 2 + q) * 16 + (a * 4 + c4)) << 6) + (l * 8 + r)] = cores[idx];
    }
    if (idx < 2 * BATCH * H * 4 * 64) {
        int j = idx & 63, a = (idx >> 6) & 3, y = (idx >> 8) & 127;
        int b = (idx >> 15) & 7, c = idx >> 18;
        const float* base = channels + (((c * BATCH + b) * H + y) * W) * 4;
        float e0 = base[(2 * j) * 4 + a];
        float e1 = base[(2 * j + 1) * 4 + a];
        int x2 = min(2 * j + 2, W - 1);
        float o1 = base[x2 * 4 + a];
        g_chE[c][b][y][a][j] = pk2(e0, e1);
        g_chO[c][b][y][a][j] = pk2(e1, o1);
    }
}

__global__ void __launch_bounds__(NTHREADS, 2) convsbs_kernel(float* __restrict__ out)
{
    extern __shared__ float smem[];
    const int tid = threadIdx.x;
    const int warp = tid >> 5;
    const int lane = tid & 31;
    ull* Wb = (ull*)smem + warp * WARP_ULL;

    const int g2 = lane >> 4;        // q (A-stage) / s (B-stage) / q (final)
    const int i2 = (lane >> 1) & 7;  // i (A) / k (B) / i (final)
    const int h2 = lane & 1;         // k-half (A) / i-half (B)

    const float2* __restrict__ gc = (const float2*)g_core;
    const ull z = pk2(0.f, 0.f);
    const int nwork = gridDim.x * WARPS_PER_CTA;

    for (int g = blockIdx.x * WARPS_PER_CTA + warp; g < TOT_GROUPS; g += nwork) {
        int b   = g / ROWG;
        int rem = g - b * ROWG;
        int y   = rem / GXG;
        int gx  = rem - y * GXG;
        int x0  = gx * 6;                   // group covers out-x x0..x0+5 (3 pairs)
        const int jbase = x0 >> 1;

        // ========== Stage 1: M for pairs pr=0..2 at (x0+2pr, x0+2pr+1) ==========
        #pragma unroll
        for (int t = 0; t < 4; t++) {
            const int py = y + (t >> 1);
            const ull* T0 = (t & 1) ? &g_chO[0][b][py][0][0] : &g_chE[0][b][py][0][0];
            const ull* T1 = (t & 1) ? &g_chO[1][b][py][0][0] : &g_chE[1][b][py][0][0];

            ull c0[NPAIR][4], c1[NPAIR][4];
            #pragma unroll
            for (int p = 0; p < NPAIR; p++) {
                const int jp = min(jbase + p, 63);
                #pragma unroll
                for (int a = 0; a < 4; a++) {
                    c0[p][a] = T0[a * 64 + jp];
                    c1[p][a] = T1[a * 64 + jp];
                }
            }

            #pragma unroll
            for (int q = 0; q < 2; q++) {
                const int bi = t * 2 + q;
                const float2* gcp = gc + (bi * 16) * 32 + lane;
                ull acc[NPAIR][2];
                #pragma unroll
                for (int p = 0; p < NPAIR; p++) { acc[p][0] = z; acc[p][1] = z; }
                #pragma unroll
                for (int ac = 0; ac < 16; ac++) {
                    float2 cc = __ldg(gcp + ac * 32);   // cores for lr=2*lane, 2*lane+1
                    ull cx2 = pk2(cc.x, cc.x);
                    ull cy2 = pk2(cc.y, cc.y);
                    const int a = ac >> 2, c = ac & 3;
                    #pragma unroll
                    for (int p = 0; p < NPAIR; p++) {
                        ull vv = mul2(c0[p][a], c1[p][c]);
                        acc[p][0] = fma2(cx2, vv, acc[p][0]);
                        acc[p][1] = fma2(cy2, vv, acc[p][1]);
                    }
                }
                const int midx = bi * 64 + 2 * lane;
                #pragma unroll
                for (int p = 0; p < NPAIR; p++)
                    *(ulonglong2*)(Wb + p * PAIR_ULL + midx) =
                        make_ulonglong2(acc[p][0], acc[p][1]);
            }
        }
        __syncwarp();

        // ========== Stage 2 per pair ==========
        #pragma unroll 1
        for (int pr = 0; pr < NPAIR; pr++) {
            ull* M = Wb + pr * PAIR_ULL;

            // ---- A-stage: lane (q=g2, i=i2, kh=h2), both p accumulated ----
            ull a2[2][4];
            {
                ull rm0[2][8];
                #pragma unroll
                for (int p = 0; p < 2; p++) {
                    #pragma unroll
                    for (int c = 0; c < 4; c++) {
                        ulonglong2 u = *(const ulonglong2*)(M + p * 64 + i2 * 8 + 2 * c);
                        rm0[p][2 * c] = u.x; rm0[p][2 * c + 1] = u.y;
                    }
                }
                #pragma unroll
                for (int p = 0; p < 2; p++)
                    #pragma unroll
                    for (int kk = 0; kk < 4; kk++) a2[p][kk] = z;
                #pragma unroll
                for (int j = 0; j < 8; j++) {
                    ulonglong2 m1a = *(const ulonglong2*)(M + (2 + g2) * 64 + j * 8 + h2 * 4);
                    ulonglong2 m1b = *(const ulonglong2*)(M + (2 + g2) * 64 + j * 8 + h2 * 4 + 2);
                    #pragma unroll
                    for (int p = 0; p < 2; p++) {
                        a2[p][0] = fma2(rm0[p][j], m1a.x, a2[p][0]);
                        a2[p][1] = fma2(rm0[p][j], m1a.y, a2[p][1]);
                        a2[p][2] = fma2(rm0[p][j], m1b.x, a2[p][2]);
                        a2[p][3] = fma2(rm0[p][j], m1b.y, a2[p][3]);
                    }
                }
            }

            // ---- B-stage: lane (s=g2, k=i2, ih=h2), both r accumulated ----
            ull bt[2][4];
            {
                ull rm2[2][8];
                #pragma unroll
                for (int r = 0; r < 2; r++) {
                    #pragma unroll
                    for (int c = 0; c < 4; c++) {
                        ulonglong2 u = *(const ulonglong2*)(M + (4 + r) * 64 + i2 * 8 + 2 * c);
                        rm2[r][2 * c] = u.x; rm2[r][2 * c + 1] = u.y;
                    }
                }
                #pragma unroll
                for (int r = 0; r < 2; r++)
                    #pragma unroll
                    for (int ii = 0; ii < 4; ii++) bt[r][ii] = z;
                #pragma unroll
                for (int l = 0; l < 8; l++) {
                    ulonglong2 m3a = *(const ulonglong2*)(M + (6 + g2) * 64 + l * 8 + h2 * 4);
                    ulonglong2 m3b = *(const ulonglong2*)(M + (6 + g2) * 64 + l * 8 + h2 * 4 + 2);
                    #pragma unroll
                    for (int r = 0; r < 2; r++) {
                        bt[r][0] = fma2(rm2[r][l], m3a.x, bt[r][0]);
                        bt[r][1] = fma2(rm2[r][l], m3a.y, bt[r][1]);
                        bt[r][2] = fma2(rm2[r][l], m3b.x, bt[r][2]);
                        bt[r][3] = fma2(rm2[r][l], m3b.y, bt[r][3]);
                    }
                }
            }
            __syncwarp();

            // ---- store B: Bsm[rs][k][i] at rs*82 + k*10 + i  (rs = r*2 + s) ----
            // (overwrites only M blocks 0..5, all dead by now)
            #pragma unroll
            for (int r = 0; r < 2; r++) {
                const int base = (r * 2 + g2) * 82 + i2 * 10 + h2 * 4;
                *(ulonglong2*)(M + base)     = make_ulonglong2(bt[r][0], bt[r][1]);
                *(ulonglong2*)(M + base + 2) = make_ulonglong2(bt[r][2], bt[r][3]);
            }
            __syncwarp();

            // ---- final partials at lane (q=g2, i=i2, kh=h2) ----
            ull part[2][4];
            #pragma unroll
            for (int p = 0; p < 2; p++)
                #pragma unroll
                for (int rs = 0; rs < 4; rs++) part[p][rs] = z;
            #pragma unroll
            for (int rs = 0; rs < 4; rs++) {
                #pragma unroll
                for (int kk = 0; kk < 4; kk++) {
                    ull Bv = M[rs * 82 + (h2 * 4 + kk) * 10 + i2];
                    part[0][rs] = fma2(a2[0][kk], Bv, part[0][rs]);
                    part[1][rs] = fma2(a2[1][kk], Bv, part[1][rs]);
                }
            }
            #pragma unroll
            for (int p = 0; p < 2; p++)
                #pragma unroll
                for (int rs = 0; rs < 4; rs++)
                    part[p][rs] = add2(part[p][rs],
                                       __shfl_xor_sync(0xffffffffu, part[p][rs], 1));
            if (h2 == 0) {
                const int pbase = 336 + (g2 * 8 + i2) * 10 + g2 * 8;
                *(ulonglong2*)(M + pbase)     = make_ulonglong2(part[0][0], part[0][1]);
                *(ulonglong2*)(M + pbase + 2) = make_ulonglong2(part[0][2], part[0][3]);
                *(ulonglong2*)(M + pbase + 4) = make_ulonglong2(part[1][0], part[1][1]);
                *(ulonglong2*)(M + pbase + 6) = make_ulonglong2(part[1][2], part[1][3]);
            }
            __syncwarp();

            // ---- output: lanes 0..15, q=lane>>3, o8=lane&7 (p=o8>>2, rs=o8&3) ----
            if (lane < 16) {
                const int q = lane >> 3, o8 = lane & 7;
                ull s = z;
                #pragma unroll
                for (int i = 0; i < 8; i++)
                    s = add2(s, M[336 + (q * 8 + i) * 10 + q * 8 + o8]);
                const int p = o8 >> 2, rs = o8 & 3;
                const int outIdx = p * 8 + q * 4 + rs;
                const int xx = x0 + pr * 2;
                if (xx < OW) {
                    const int pix0 = (b * OH + y) * OW + xx;
                    float2 pv = up2(s);
                    out[pix0 * 16 + outIdx] = pv.x;
                    if (xx + 1 < OW)
                        out[(pix0 + 1) * 16 + outIdx] = pv.y;
                }
            }
            __syncwarp();
        }
    }
}

extern "C" void kernel_launch(void* const* d_in, const int* in_sizes, int n_in,
                              void* d_out, int out_size)
{
    const float* channels = (const float*)d_in[0];
    const float* cores    = (const float*)d_in[1];
    float* out            = (float*)d_out;

    static bool attr_set = false;
    if (!attr_set) {
        cudaFuncSetAttribute(convsbs_kernel,
                             cudaFuncAttributeMaxDynamicSharedMemorySize,
                             SMEM_F * sizeof(float));
        attr_set = true;
    }
    setup_kernel<<<512, 1024>>>(channels, cores);
    convsbs_kernel<<<NCTAS, NTHREADS, SMEM_F * sizeof(float)>>>(out);
}

// round 16
// speedup vs baseline: 1.0083x; 1.0083x over previous
#include <cuda_runtime.h>

// ConvSBS fused contraction, P=6 (3 pixel-pairs/warp), f32x2 SIMD, 192-thread CTAs.
// Cores in smem (swizzled LDS.128 scans); channels in packed pixel-pair tables.
// channels: [2, 8, 128, 128, 4] f32 ; cores: [4, 2, 8, 8, 4, 4] f32 ; out: [8,127,127,16] f32

typedef unsigned long long ull;

__device__ __forceinline__ ull pk2(float lo, float hi) {
    ull d; asm("mov.b64 %0, {%1, %2};" : "=l"(d) : "f"(lo), "f"(hi)); return d;
}
__device__ __forceinline__ float2 up2(ull v) {
    float2 r; asm("mov.b64 {%0, %1}, %2;" : "=f"(r.x), "=f"(r.y) : "l"(v)); return r;
}
__device__ __forceinline__ ull fma2(ull a, ull b, ull c) {
    ull d; asm("fma.rn.f32x2 %0, %1, %2, %3;" : "=l"(d) : "l"(a), "l"(b), "l"(c)); return d;
}
__device__ __forceinline__ ull mul2(ull a, ull b) {
    ull d; asm("mul.rn.f32x2 %0, %1, %2;" : "=l"(d) : "l"(a), "l"(b)); return d;
}
__device__ __forceinline__ ull add2(ull a, ull b) {
    ull d; asm("add.rn.f32x2 %0, %1, %2;" : "=l"(d) : "l"(a), "l"(b)); return d;
}

#define BATCH 8
#define H 128
#define W 128
#define OH 127
#define OW 127
#define GXG 22                               // groups of 6 px per row (22*6=132 >= 127)
#define ROWG (OH * GXG)
#define TOT_GROUPS (BATCH * ROWG)            // 22352

#define WARPS_PER_CTA 6
#define NTHREADS (WARPS_PER_CTA * 32)        // 192
#define NCTAS 296
#define NPAIR 3

// Packed pixel-pair channel tables: [ch][b][y][a][j]
//   chE[..][j] = (px 2j,   px 2j+1) ; chO[..][j] = (px 2j+1, px min(2j+2,127))
__device__ ull g_chE[2][BATCH][H][4][64];
__device__ ull g_chO[2][BATCH][H][4][64];

// Cores in smem, swizzled (4 KB per block bi): lane L owns lr (2L,2L+1);
// chunk c8 at ull idx bi*512 + L*16 + ((c8+L)&7)*2.
// chunk (float4) = { core[ac=2c8](lr0), core[2c8](lr1), core[2c8+1](lr0), core[2c8+1](lr1) }
//
// Per-pair scratch: 512 ull.
//   M element (bi,row,col) at ull idx bi*64 + row*8 + col.
//   Overlays (written only after the overlapped M blocks are dead):
//     Bsm[rs][k][i] at rs*82 + k*10 + i   (max 325)
//     Psm at 336 + (q*8+i)*10 + q*8 + o8  (max 501)
#define PAIR_ULL 512
#define WARP_ULL (NPAIR * PAIR_ULL)
#define CORES_F 8192
#define SMEM_F  (CORES_F + WARPS_PER_CTA * WARP_ULL * 2)

__global__ void transpose_kernel(const float* __restrict__ channels) {
    int idx = blockIdx.x * blockDim.x + threadIdx.x;   // 2*8*128*4*64 = 524288
    if (idx >= 2 * BATCH * H * 4 * 64) return;
    int j = idx & 63, a = (idx >> 6) & 3, y = (idx >> 8) & 127;
    int b = (idx >> 15) & 7, c = idx >> 18;
    const float* base = channels + (((c * BATCH + b) * H + y) * W) * 4;
    float e0 = base[(2 * j) * 4 + a];
    float e1 = base[(2 * j + 1) * 4 + a];
    int x2 = min(2 * j + 2, W - 1);
    float o1 = base[x2 * 4 + a];
    g_chE[c][b][y][a][j] = pk2(e0, e1);
    g_chO[c][b][y][a][j] = pk2(e1, o1);
}

__global__ void __launch_bounds__(NTHREADS, 2) convsbs_kernel(
    const float* __restrict__ cores,
    float* __restrict__ out)
{
    extern __shared__ float smem[];
    const int tid = threadIdx.x;
    ull* coreU = (ull*)smem;

    // cores relayout: [t][q][l][r][a][c4] -> swizzled per-lane chunks
    for (int idx = tid; idx < 8192; idx += NTHREADS) {
        int c4 = idx & 3, a = (idx >> 2) & 3, r = (idx >> 4) & 7;
        int l = (idx >> 7) & 7, q = (idx >> 10) & 1, t = idx >> 11;
        int bi = t * 2 + q;
        int lr = l * 8 + r;
        int L = lr >> 1, half = lr & 1;
        int ac = a * 4 + c4;
        int chunk = ac >> 1, pos = ac & 1;
        int uidx = bi * 512 + L * 16 + (((chunk + L) & 7) << 1) + pos;
        smem[uidx * 2 + half] = cores[idx];
    }
    __syncthreads();

    const int warp = tid >> 5;
    const int lane = tid & 31;
    ull* Wb = (ull*)(smem + CORES_F) + warp * WARP_ULL;

    const int g2 = lane >> 4;        // q (A-stage) / s (B-stage) / q (final)
    const int i2 = (lane >> 1) & 7;  // i (A) / k (B) / i (final)
    const int h2 = lane & 1;         // k-half (A) / i-half (B)

    const ull z = pk2(0.f, 0.f);
    const int nwork = gridDim.x * WARPS_PER_CTA;

    for (int g = blockIdx.x * WARPS_PER_CTA + warp; g < TOT_GROUPS; g += nwork) {
        int b   = g / ROWG;
        int rem = g - b * ROWG;
        int y   = rem / GXG;
        int gx  = rem - y * GXG;
        int x0  = gx * 6;                   // group covers out-x x0..x0+5 (3 pairs)
        const int jbase = x0 >> 1;

        // ========== Stage 1: M for pairs pr=0..2 at (x0+2pr, x0+2pr+1) ==========
        #pragma unroll 1
        for (int t = 0; t < 4; t++) {
            const int py = y + (t >> 1);
            const ull* T0 = (t & 1) ? &g_chO[0][b][py][0][0] : &g_chE[0][b][py][0][0];
            const ull* T1 = (t & 1) ? &g_chO[1][b][py][0][0] : &g_chE[1][b][py][0][0];

            ull c0[NPAIR][4], c1[NPAIR][4];
            #pragma unroll
            for (int p = 0; p < NPAIR; p++) {
                const int jp = min(jbase + p, 63);
                #pragma unroll
                for (int a = 0; a < 4; a++) {
                    c0[p][a] = T0[a * 64 + jp];
                    c1[p][a] = T1[a * 64 + jp];
                }
            }

            #pragma unroll
            for (int q = 0; q < 2; q++) {
                const int bi = t * 2 + q;
                const float4* cp4 = (const float4*)(coreU + bi * 512 + lane * 16);
                ull acc[NPAIR][2];
                #pragma unroll
                for (int p = 0; p < NPAIR; p++) { acc[p][0] = z; acc[p][1] = z; }
                #pragma unroll
                for (int c8 = 0; c8 < 8; c8++) {
                    float4 f = cp4[(c8 + lane) & 7];   // ac=2c8: (f.x,f.y); 2c8+1: (f.z,f.w)
                    const int a0  = c8 >> 1;           // a of both ac=2c8, 2c8+1
                    const int cc0 = (2 * c8) & 3;      // c of ac=2c8 (cc0+1 for 2c8+1)
                    ull cx2 = pk2(f.x, f.x);
                    ull cy2 = pk2(f.y, f.y);
                    ull cz2 = pk2(f.z, f.z);
                    ull cw2 = pk2(f.w, f.w);
                    #pragma unroll
                    for (int p = 0; p < NPAIR; p++) {
                        ull vv0 = mul2(c0[p][a0], c1[p][cc0]);
                        ull vv1 = mul2(c0[p][a0], c1[p][cc0 + 1]);
                        acc[p][0] = fma2(cx2, vv0, acc[p][0]);
                        acc[p][1] = fma2(cy2, vv0, acc[p][1]);
                        acc[p][0] = fma2(cz2, vv1, acc[p][0]);
                        acc[p][1] = fma2(cw2, vv1, acc[p][1]);
                    }
                }
                const int midx = bi * 64 + 2 * lane;   // (row=lane>>2)*8 + 2*(lane&3)
                #pragma unroll
                for (int p = 0; p < NPAIR; p++)
                    *(ulonglong2*)(Wb + p * PAIR_ULL + midx) =
                        make_ulonglong2(acc[p][0], acc[p][1]);
            }
        }
        __syncwarp();

        // ========== Stage 2 per pair ==========
        #pragma unroll 1
        for (int pr = 0; pr < NPAIR; pr++) {
            ull* M = Wb + pr * PAIR_ULL;

            // ---- A-stage: lane (q=g2, i=i2, kh=h2), both p accumulated ----
            ull a2[2][4];
            {
                ull rm0[2][8];
                #pragma unroll
                for (int p = 0; p < 2; p++) {
                    #pragma unroll
                    for (int c = 0; c < 4; c++) {
                        ulonglong2 u = *(const ulonglong2*)(M + p * 64 + i2 * 8 + 2 * c);
                        rm0[p][2 * c] = u.x; rm0[p][2 * c + 1] = u.y;
                    }
                }
                #pragma unroll
                for (int p = 0; p < 2; p++)
                    #pragma unroll
                    for (int kk = 0; kk < 4; kk++) a2[p][kk] = z;
                #pragma unroll
                for (int j = 0; j < 8; j++) {
                    ulonglong2 m1a = *(const ulonglong2*)(M + (2 + g2) * 64 + j * 8 + h2 * 4);
                    ulonglong2 m1b = *(const ulonglong2*)(M + (2 + g2) * 64 + j * 8 + h2 * 4 + 2);
                    #pragma unroll
                    for (int p = 0; p < 2; p++) {
                        a2[p][0] = fma2(rm0[p][j], m1a.x, a2[p][0]);
                        a2[p][1] = fma2(rm0[p][j], m1a.y, a2[p][1]);
                        a2[p][2] = fma2(rm0[p][j], m1b.x, a2[p][2]);
                        a2[p][3] = fma2(rm0[p][j], m1b.y, a2[p][3]);
                    }
                }
            }

            // ---- B-stage: lane (s=g2, k=i2, ih=h2), both r accumulated ----
            ull bt[2][4];
            {
                ull rm2[2][8];
                #pragma unroll
                for (int r = 0; r < 2; r++) {
                    #pragma unroll
                    for (int c = 0; c < 4; c++) {
                        ulonglong2 u = *(const ulonglong2*)(M + (4 + r) * 64 + i2 * 8 + 2 * c);
                        rm2[r][2 * c] = u.x; rm2[r][2 * c + 1] = u.y;
                    }
                }
                #pragma unroll
                for (int r = 0; r < 2; r++)
                    #pragma unroll
                    for (int ii = 0; ii < 4; ii++) bt[r][ii] = z;
                #pragma unroll
                for (int l = 0; l < 8; l++) {
                    ulonglong2 m3a = *(const ulonglong2*)(M + (6 + g2) * 64 + l * 8 + h2 * 4);
                    ulonglong2 m3b = *(const ulonglong2*)(M + (6 + g2) * 64 + l * 8 + h2 * 4 + 2);
                    #pragma unroll
                    for (int r = 0; r < 2; r++) {
                        bt[r][0] = fma2(rm2[r][l], m3a.x, bt[r][0]);
                        bt[r][1] = fma2(rm2[r][l], m3a.y, bt[r][1]);
                        bt[r][2] = fma2(rm2[r][l], m3b.x, bt[r][2]);
                        bt[r][3] = fma2(rm2[r][l], m3b.y, bt[r][3]);
                    }
                }
            }
            __syncwarp();

            // ---- store B: Bsm[rs][k][i] at rs*82 + k*10 + i  (rs = r*2 + s) ----
            #pragma unroll
            for (int r = 0; r < 2; r++) {
                const int base = (r * 2 + g2) * 82 + i2 * 10 + h2 * 4;
                *(ulonglong2*)(M + base)     = make_ulonglong2(bt[r][0], bt[r][1]);
                *(ulonglong2*)(M + base + 2) = make_ulonglong2(bt[r][2], bt[r][3]);
            }
            __syncwarp();

            // ---- final partials at lane (q=g2, i=i2, kh=h2) ----
            ull part[2][4];
            #pragma unroll
            for (int p = 0; p < 2; p++)
                #pragma unroll
                for (int rs = 0; rs < 4; rs++) part[p][rs] = z;
            #pragma unroll
            for (int rs = 0; rs < 4; rs++) {
                #pragma unroll
                for (int kk = 0; kk < 4; kk++) {
                    ull Bv = M[rs * 82 + (h2 * 4 + kk) * 10 + i2];
                    part[0][rs] = fma2(a2[0][kk], Bv, part[0][rs]);
                    part[1][rs] = fma2(a2[1][kk], Bv, part[1][rs]);
                }
            }
            #pragma unroll
            for (int p = 0; p < 2; p++)
                #pragma unroll
                for (int rs = 0; rs < 4; rs++)
                    part[p][rs] = add2(part[p][rs],
                                       __shfl_xor_sync(0xffffffffu, part[p][rs], 1));
            if (h2 == 0) {
                const int pbase = 336 + (g2 * 8 + i2) * 10 + g2 * 8;
                *(ulonglong2*)(M + pbase)     = make_ulonglong2(part[0][0], part[0][1]);
                *(ulonglong2*)(M + pbase + 2) = make_ulonglong2(part[0][2], part[0][3]);
                *(ulonglong2*)(M + pbase + 4) = make_ulonglong2(part[1][0], part[1][1]);
                *(ulonglong2*)(M + pbase + 6) = make_ulonglong2(part[1][2], part[1][3]);
            }
            __syncwarp();

            // ---- output: lanes 0..15, q=lane>>3, o8=lane&7 (p=o8>>2, rs=o8&3) ----
            if (lane < 16) {
                const int q = lane >> 3, o8 = lane & 7;
                ull s = z;
                #pragma unroll
                for (int i = 0; i < 8; i++)
                    s = add2(s, M[336 + (q * 8 + i) * 10 + q * 8 + o8]);
                const int p = o8 >> 2, rs = o8 & 3;
                const int outIdx = p * 8 + q * 4 + rs;
                const int xx = x0 + pr * 2;
                if (xx < OW) {
                    const int pix0 = (b * OH + y) * OW + xx;
                    float2 pv = up2(s);
                    out[pix0 * 16 + outIdx] = pv.x;
                    if (xx + 1 < OW)
                        out[(pix0 + 1) * 16 + outIdx] = pv.y;
                }
            }
            __syncwarp();
        }
    }
}

extern "C" void kernel_launch(void* const* d_in, const int* in_sizes, int n_in,
                              void* d_out, int out_size)
{
    const float* channels = (const float*)d_in[0];
    const float* cores    = (const float*)d_in[1];
    float* out            = (float*)d_out;

    static bool attr_set = false;
    if (!attr_set) {
        cudaFuncSetAttribute(convsbs_kernel,
                             cudaFuncAttributeMaxDynamicSharedMemorySize,
                             SMEM_F * sizeof(float));
        attr_set = true;
    }
    transpose_kernel<<<512, 1024>>>(channels);
    convsbs_kernel<<<NCTAS, NTHREADS, SMEM_F * sizeof(float)>>>(cores, out);
}

// round 17
// speedup vs baseline: 1.1935x; 1.1837x over previous
#include <cuda_runtime.h>
#include <cuda_fp16.h>

// ConvSBS fused contraction, pixel-pair SIMD (f32x2), R13 structure +
// cores stored in smem as fp16 (halves the dominant core-scan L1 traffic).
// All arithmetic and all other data remain fp32.
// channels: [2, 8, 128, 128, 4] f32 ; cores: [4, 2, 8, 8, 4, 4] f32 ; out: [8,127,127,16] f32

typedef unsigned long long ull;

__device__ __forceinline__ ull pk2(float lo, float hi) {
    ull d; asm("mov.b64 %0, {%1, %2};" : "=l"(d) : "f"(lo), "f"(hi)); return d;
}
__device__ __forceinline__ float2 up2(ull v) {
    float2 r; asm("mov.b64 {%0, %1}, %2;" : "=f"(r.x), "=f"(r.y) : "l"(v)); return r;
}
__device__ __forceinline__ ull fma2(ull a, ull b, ull c) {
    ull d; asm("fma.rn.f32x2 %0, %1, %2, %3;" : "=l"(d) : "l"(a), "l"(b), "l"(c)); return d;
}
__device__ __forceinline__ ull mul2(ull a, ull b) {
    ull d; asm("mul.rn.f32x2 %0, %1, %2;" : "=l"(d) : "l"(a), "l"(b)); return d;
}
__device__ __forceinline__ ull add2(ull a, ull b) {
    ull d; asm("add.rn.f32x2 %0, %1, %2;" : "=l"(d) : "l"(a), "l"(b)); return d;
}

#define BATCH 8
#define H 128
#define W 128
#define OH 127
#define OW 127
#define GX 32
#define TOT_GROUPS (BATCH * OH * GX)

#define WARPS_PER_CTA 8
#define NTHREADS (WARPS_PER_CTA * 32)
#define NCTAS 296

// Packed pixel-pair channel tables: [ch][b][y][a][j]
//   chE[..][j] = (px 2j,   px 2j+1) ; chO[..][j] = (px 2j+1, px min(2j+2,127))
__device__ ull g_chE[2][BATCH][H][4][64];
__device__ ull g_chO[2][BATCH][H][4][64];

// Cores in smem as fp16 (16 KB total, 2 KB per block bi):
//   lane L owns lr entries (2L, 2L+1). Its 16 half2 (ac=0..15; half2 = (lr0,lr1))
//   are stored as 4 chunks of 4 half2 (= one uint4 / LDS.128 each).
//   chunk k of lane L at half-index: bi*1024 + L*32 + ((k + (L>>1)) & 3)*8,
//   with ac = 4k + pos, pos = ac&3, halves: low = lr even, high = lr odd.
//   (Swizzle (k + (L>>1))&3 => every LDS.128 hits each 16B bank-quad with
//    exactly 4 lanes = the 4-wavefront width floor.)
//
// Per-pair scratch: 640 ull (PROVEN padded layout).
//   M element (bi,row,col) at ull idx bi*80 + row*10 + col.
//   Overlays: Bsm[rs][k][i] at rs*82 + k*10 + i ; Psm at 336 + (q*8+i)*10 + q*8 + o8.
#define MBS 80
#define PAIR_ULL 640
#define WARP_ULL (2 * PAIR_ULL)
#define CORES_F 4096                      /* floats reserved = 8192 halfs = 16 KB */
#define SMEM_F  (CORES_F + WARPS_PER_CTA * WARP_ULL * 2)

__global__ void transpose_kernel(const float* __restrict__ channels) {
    int idx = blockIdx.x * blockDim.x + threadIdx.x;   // 2*8*128*4*64 = 524288
    if (idx >= 2 * BATCH * H * 4 * 64) return;
    int j = idx & 63, a = (idx >> 6) & 3, y = (idx >> 8) & 127;
    int b = (idx >> 15) & 7, c = idx >> 18;
    const float* base = channels + (((c * BATCH + b) * H + y) * W) * 4;
    float e0 = base[(2 * j) * 4 + a];
    float e1 = base[(2 * j + 1) * 4 + a];
    int x2 = min(2 * j + 2, W - 1);
    float o1 = base[x2 * 4 + a];
    g_chE[c][b][y][a][j] = pk2(e0, e1);
    g_chO[c][b][y][a][j] = pk2(e1, o1);
}

__global__ void __launch_bounds__(NTHREADS, 2) convsbs_kernel(
    const float* __restrict__ cores,
    float* __restrict__ out)
{
    extern __shared__ float smem[];
    const int tid = threadIdx.x;
    __half* coreH = (__half*)smem;

    // cores relayout: [t][q][l][r][a][c4] fp32 -> swizzled fp16 per-lane chunks
    for (int idx = tid; idx < 8192; idx += NTHREADS) {
        int c4 = idx & 3, a = (idx >> 2) & 3, r = (idx >> 4) & 7;
        int l = (idx >> 7) & 7, q = (idx >> 10) & 1, t = idx >> 11;
        int bi = t * 2 + q;
        int lr = l * 8 + r;
        int L = lr >> 1, half = lr & 1;
        int ac = a * 4 + c4;
        int chunk = ac >> 2, pos = ac & 3;
        int hidx = bi * 1024 + L * 32 + (((chunk + (L >> 1)) & 3) << 3) + pos * 2 + half;
        coreH[hidx] = __float2half(cores[idx]);
    }
    __syncthreads();

    const int warp = tid >> 5;
    const int lane = tid & 31;
    ull* Wb = (ull*)(smem + CORES_F) + warp * WARP_ULL;

    const int g2 = lane >> 4;        // q (A-stage) / s (B-stage) / q (final)
    const int i2 = (lane >> 1) & 7;  // i (A) / k (B) / i (final)
    const int h2 = lane & 1;         // k-half (A) / i-half (B)

    const ull z = pk2(0.f, 0.f);
    const int nwork = gridDim.x * WARPS_PER_CTA;

    for (int g = blockIdx.x * WARPS_PER_CTA + warp; g < TOT_GROUPS; g += nwork) {
        int b   = g / (OH * GX);
        int rem = g - b * (OH * GX);
        int y   = rem >> 5;
        int x0  = (rem & 31) << 2;
        const int jbase = x0 >> 1;

        // ========== Stage 1: M for pairs A=(x0+wt, x0+1+wt), B=(x0+2+wt, x0+3+wt) ==========
        #pragma unroll
        for (int t = 0; t < 4; t++) {
            const int py = y + (t >> 1);
            const ull* T0 = (t & 1) ? &g_chO[0][b][py][0][jbase] : &g_chE[0][b][py][0][jbase];
            const ull* T1 = (t & 1) ? &g_chO[1][b][py][0][jbase] : &g_chE[1][b][py][0][jbase];

            // packed channels: pair A at j=jbase, pair B at j=jbase+1 (direct LDG.64)
            ull c0A[4], c1A[4], c0B[4], c1B[4];
            #pragma unroll
            for (int a = 0; a < 4; a++) {
                c0A[a] = T0[a * 64];
                c0B[a] = T0[a * 64 + 1];
                c1A[a] = T1[a * 64];
                c1B[a] = T1[a * 64 + 1];
            }

            ull vA[16], vB[16];
            #pragma unroll
            for (int a = 0; a < 4; a++)
                #pragma unroll
                for (int c = 0; c < 4; c++) {
                    vA[a * 4 + c] = mul2(c0A[a], c1A[c]);
                    vB[a * 4 + c] = mul2(c0B[a], c1B[c]);
                }

            const int row = lane >> 2;        // l of entry lr = 2*lane
            const int col = 2 * (lane & 3);   // r of entry lr = 2*lane
            #pragma unroll
            for (int q = 0; q < 2; q++) {
                const int bi = t * 2 + q;
                const uint4* cp4 = (const uint4*)(coreH + bi * 1024 + lane * 32);
                ull aA0 = z, aA1 = z, aB0 = z, aB1 = z;
                #pragma unroll
                for (int k = 0; k < 4; k++) {
                    uint4 f = cp4[(k + (lane >> 1)) & 3];   // ac = 4k .. 4k+3 (half2 each)
                    unsigned int hw[4] = {f.x, f.y, f.z, f.w};
                    #pragma unroll
                    for (int e = 0; e < 4; e++) {
                        float2 gpair = __half22float2(*reinterpret_cast<__half2*>(&hw[e]));
                        ull cx2 = pk2(gpair.x, gpair.x);   // core[ac](lr0)
                        ull cy2 = pk2(gpair.y, gpair.y);   // core[ac](lr1)
                        const int ac = 4 * k + e;
                        aA0 = fma2(cx2, vA[ac], aA0);
                        aA1 = fma2(cy2, vA[ac], aA1);
                        aB0 = fma2(cx2, vB[ac], aB0);
                        aB1 = fma2(cy2, vB[ac], aB1);
                    }
                }
                const int midx = bi * MBS + row * 10 + col;
                *(ulonglong2*)(Wb + midx)            = make_ulonglong2(aA0, aA1);
                *(ulonglong2*)(Wb + PAIR_ULL + midx) = make_ulonglong2(aB0, aB1);
            }
        }
        __syncwarp();

        // ========== Stage 2 per pair ==========
        #pragma unroll
        for (int pr = 0; pr < 2; pr++) {
            ull* M = Wb + pr * PAIR_ULL;

            // ---- A-stage: lane (q=g2, i=i2, kh=h2), both p accumulated ----
            ull a2[2][4];
            {
                ull rm0[2][8];
                #pragma unroll
                for (int p = 0; p < 2; p++) {
                    #pragma unroll
                    for (int c = 0; c < 4; c++) {
                        ulonglong2 u = *(const ulonglong2*)(M + p * MBS + i2 * 10 + 2 * c);
                        rm0[p][2 * c] = u.x; rm0[p][2 * c + 1] = u.y;
                    }
                }
                #pragma unroll
                for (int p = 0; p < 2; p++)
                    #pragma unroll
                    for (int kk = 0; kk < 4; kk++) a2[p][kk] = z;
                #pragma unroll
                for (int j = 0; j < 8; j++) {
                    ulonglong2 m1a = *(const ulonglong2*)(M + (2 + g2) * MBS + j * 10 + h2 * 4);
                    ulonglong2 m1b = *(const ulonglong2*)(M + (2 + g2) * MBS + j * 10 + h2 * 4 + 2);
                    #pragma unroll
                    for (int p = 0; p < 2; p++) {
                        a2[p][0] = fma2(rm0[p][j], m1a.x, a2[p][0]);
                        a2[p][1] = fma2(rm0[p][j], m1a.y, a2[p][1]);
                        a2[p][2] = fma2(rm0[p][j], m1b.x, a2[p][2]);
                        a2[p][3] = fma2(rm0[p][j], m1b.y, a2[p][3]);
                    }
                }
            }

            // ---- B-stage: lane (s=g2, k=i2, ih=h2), both r accumulated ----
            ull bt[2][4];
            {
                ull rm2[2][8];
                #pragma unroll
                for (int r = 0; r < 2; r++) {
                    #pragma unroll
                    for (int c = 0; c < 4; c++) {
                        ulonglong2 u = *(const ulonglong2*)(M + (4 + r) * MBS + i2 * 10 + 2 * c);
                        rm2[r][2 * c] = u.x; rm2[r][2 * c + 1] = u.y;
                    }
                }
                #pragma unroll
                for (int r = 0; r < 2; r++)
                    #pragma unroll
                    for (int ii = 0; ii < 4; ii++) bt[r][ii] = z;
                #pragma unroll
                for (int l = 0; l < 8; l++) {
                    ulonglong2 m3a = *(const ulonglong2*)(M + (6 + g2) * MBS + l * 10 + h2 * 4);
                    ulonglong2 m3b = *(const ulonglong2*)(M + (6 + g2) * MBS + l * 10 + h2 * 4 + 2);
                    #pragma unroll
                    for (int r = 0; r < 2; r++) {
                        bt[r][0] = fma2(rm2[r][l], m3a.x, bt[r][0]);
                        bt[r][1] = fma2(rm2[r][l], m3a.y, bt[r][1]);
                        bt[r][2] = fma2(rm2[r][l], m3b.x, bt[r][2]);
                        bt[r][3] = fma2(rm2[r][l], m3b.y, bt[r][3]);
                    }
                }
            }
            __syncwarp();

            // ---- store B: Bsm[rs][k][i] at rs*82 + k*10 + i  (rs = r*2 + s) ----
            #pragma unroll
            for (int r = 0; r < 2; r++) {
                const int base = (r * 2 + g2) * 82 + i2 * 10 + h2 * 4;
                *(ulonglong2*)(M + base)     = make_ulonglong2(bt[r][0], bt[r][1]);
                *(ulonglong2*)(M + base + 2) = make_ulonglong2(bt[r][2], bt[r][3]);
            }
            __syncwarp();

            // ---- final partials at lane (q=g2, i=i2, kh=h2) ----
            ull part[2][4];
            #pragma unroll
            for (int p = 0; p < 2; p++)
                #pragma unroll
                for (int rs = 0; rs < 4; rs++) part[p][rs] = z;
            #pragma unroll
            for (int rs = 0; rs < 4; rs++) {
                #pragma unroll
                for (int kk = 0; kk < 4; kk++) {
                    ull Bv = M[rs * 82 + (h2 * 4 + kk) * 10 + i2];
                    part[0][rs] = fma2(a2[0][kk], Bv, part[0][rs]);
                    part[1][rs] = fma2(a2[1][kk], Bv, part[1][rs]);
                }
            }
            #pragma unroll
            for (int p = 0; p < 2; p++)
                #pragma unroll
                for (int rs = 0; rs < 4; rs++)
                    part[p][rs] = add2(part[p][rs],
                                       __shfl_xor_sync(0xffffffffu, part[p][rs], 1));
            if (h2 == 0) {
                const int pbase = 336 + (g2 * 8 + i2) * 10 + g2 * 8;
                *(ulonglong2*)(M + pbase)     = make_ulonglong2(part[0][0], part[0][1]);
                *(ulonglong2*)(M + pbase + 2) = make_ulonglong2(part[0][2], part[0][3]);
                *(ulonglong2*)(M + pbase + 4) = make_ulonglong2(part[1][0], part[1][1]);
                *(ulonglong2*)(M + pbase + 6) = make_ulonglong2(part[1][2], part[1][3]);
            }
            __syncwarp();

            // ---- output: lanes 0..15, q=lane>>3, o8=lane&7 (p=o8>>2, rs=o8&3) ----
            if (lane < 16) {
                const int q = lane >> 3, o8 = lane & 7;
                ull s = z;
                #pragma unroll
                for (int i = 0; i < 8; i++)
                    s = add2(s, M[336 + (q * 8 + i) * 10 + q * 8 + o8]);
                const int p = o8 >> 2, rs = o8 & 3;
                const int outIdx = p * 8 + q * 4 + rs;
                const int xx = x0 + pr * 2;
                const int pix0 = (b * OH + y) * OW + xx;
                float2 pv = up2(s);
                out[pix0 * 16 + outIdx] = pv.x;
                if (xx + 1 < OW)
                    out[(pix0 + 1) * 16 + outIdx] = pv.y;
            }
            __syncwarp();
        }
    }
}

extern "C" void kernel_launch(void* const* d_in, const int* in_sizes, int n_in,
                              void* d_out, int out_size)
{
    const float* channels = (const float*)d_in[0];
    const float* cores    = (const float*)d_in[1];
    float* out            = (float*)d_out;

    static bool attr_set = false;
    if (!attr_set) {
        cudaFuncSetAttribute(convsbs_kernel,
                             cudaFuncAttributeMaxDynamicSharedMemorySize,
                             SMEM_F * sizeof(float));
        attr_set = true;
    }
    transpose_kernel<<<512, 1024>>>(channels);
    convsbs_kernel<<<NCTAS, NTHREADS, SMEM_F * sizeof(float)>>>(cores, out);
}